// round 14
// baseline (speedup 1.0000x reference)
#include <cuda_runtime.h>
#include <cuda_bf16.h>
#include <math.h>
#include <cstdint>

#define BDIM   2
#define SDIM   2048
#define NSTATE 1024
#define NHEAD  16
#define HDIM   64
#define MROWS  (BDIM*SDIM)            // 4096

constexpr float SCALE_QK = 0.35355339059327373f;  // 64^-0.25

// ---------------- scratch (static device globals; no allocs allowed) --------
__device__ float g_V [BDIM*NHEAD*SDIM*HDIM];   // [b][h][s][d] fp32

__device__ __nv_bfloat16 g_Qh[BDIM*NHEAD*SDIM*HDIM];  // [b][h][s][d] hi/lo, pre-scaled
__device__ __nv_bfloat16 g_Ql[BDIM*NHEAD*SDIM*HDIM];
__device__ __nv_bfloat16 g_Kh[BDIM*NHEAD*SDIM*HDIM];
__device__ __nv_bfloat16 g_Kl[BDIM*NHEAD*SDIM*HDIM];
__device__ __nv_bfloat16 g_Vth[BDIM*NHEAD*HDIM*SDIM]; // [b][h][d][s] hi/lo
__device__ __nv_bfloat16 g_Vtl[BDIM*NHEAD*HDIM*SDIM];

__device__ __nv_bfloat16 g_xh [MROWS*NSTATE];
__device__ __nv_bfloat16 g_xl [MROWS*NSTATE];
__device__ __nv_bfloat16 g_WVh[MROWS*NSTATE];         // written directly by flash
__device__ __nv_bfloat16 g_WVl[MROWS*NSTATE];
__device__ __nv_bfloat16 g_Wth[4*NSTATE*NSTATE];  // transposed weights [n][k]; q,k,v,o contiguous
__device__ __nv_bfloat16 g_Wtl[4*NSTATE*NSTATE];

// ---------------- helpers ---------------------------------------------------
__device__ __forceinline__ void split_bf16(float v, __nv_bfloat16& h, __nv_bfloat16& l) {
    h = __float2bfloat16_rn(v);
    l = __float2bfloat16_rn(v - __bfloat162float(h));
}
__device__ __forceinline__ void packsplit2(float x, float y, uint32_t& hh, uint32_t& ll) {
    __nv_bfloat16 xh, xl, yh, yl;
    split_bf16(x, xh, xl); split_bf16(y, yh, yl);
    __nv_bfloat162 hv, lv;
    hv.x = xh; hv.y = yh; lv.x = xl; lv.y = yl;
    hh = *(uint32_t*)&hv; ll = *(uint32_t*)&lv;
}
__device__ __forceinline__ void mma16816(float* c, const uint32_t* a, const uint32_t* b) {
    asm volatile(
        "mma.sync.aligned.m16n8k16.row.col.f32.bf16.bf16.f32 "
        "{%0,%1,%2,%3}, {%4,%5,%6,%7}, {%8,%9}, {%0,%1,%2,%3};"
        : "+f"(c[0]), "+f"(c[1]), "+f"(c[2]), "+f"(c[3])
        : "r"(a[0]), "r"(a[1]), "r"(a[2]), "r"(a[3]), "r"(b[0]), "r"(b[1]));
}
__device__ __forceinline__ void mma2(float* c0, float* c1, const uint32_t* a, const uint32_t* r4) {
    mma16816(c0, a, r4);
    mma16816(c1, a, r4 + 2);
}
__device__ __forceinline__ void ldsm4(uint32_t* r, uint32_t saddr) {
    asm volatile("ldmatrix.sync.aligned.m8n8.x4.shared.b16 {%0,%1,%2,%3}, [%4];"
        : "=r"(r[0]), "=r"(r[1]), "=r"(r[2]), "=r"(r[3]) : "r"(saddr));
}
__device__ __forceinline__ void cp16(void* smem_dst, const void* gsrc) {
    uint32_t s = (uint32_t)__cvta_generic_to_shared(smem_dst);
    asm volatile("cp.async.ca.shared.global [%0], [%1], 16;" :: "r"(s), "l"(gsrc) : "memory");
}
#define CP_COMMIT() asm volatile("cp.async.commit_group;" ::: "memory")
#define CP_WAIT(n)  asm volatile("cp.async.wait_group %0;" :: "n"(n) : "memory")

// ---------------- conversion kernels ----------------------------------------
__global__ void convert_x_kernel(const float* __restrict__ x) {
    size_t i = (size_t)blockIdx.x * 256 + threadIdx.x;
    float4 v = ((const float4*)x)[i];
    __nv_bfloat16 h[4], l[4];
    split_bf16(v.x, h[0], l[0]); split_bf16(v.y, h[1], l[1]);
    split_bf16(v.z, h[2], l[2]); split_bf16(v.w, h[3], l[3]);
    ((uint2*)g_xh)[i] = *(uint2*)h;
    ((uint2*)g_xl)[i] = *(uint2*)l;
}

__global__ void transpose_convert(const float* __restrict__ W0, const float* __restrict__ W1,
                                  const float* __restrict__ W2, const float* __restrict__ W3) {
    __shared__ float T[32][33];
    int w = blockIdx.z;
    const float* W = (w == 0) ? W0 : (w == 1) ? W1 : (w == 2) ? W2 : W3;
    int n0 = blockIdx.x * 32, k0 = blockIdx.y * 32;
    int tx = threadIdx.x, ty = threadIdx.y;
#pragma unroll
    for (int r = 0; r < 4; r++) {
        int kl = ty + 8 * r;
        T[kl][tx] = W[(size_t)(k0 + kl) * NSTATE + n0 + tx];
    }
    __syncthreads();
    size_t base = (size_t)w * NSTATE * NSTATE;
#pragma unroll
    for (int r = 0; r < 4; r++) {
        int nl = ty + 8 * r;
        float v = T[tx][nl];
        __nv_bfloat16 h, l;
        split_bf16(v, h, l);
        size_t o = base + (size_t)(n0 + nl) * NSTATE + k0 + tx;
        g_Wth[o] = h;
        g_Wtl[o] = l;
    }
}

// V transpose: g_V[b,h,s,d] fp32 -> g_Vt{h,l}[b,h,d,s] bf16
__global__ void vtrans() {
    __shared__ float T[32][33];
    int bh = blockIdx.z;
    int s0 = blockIdx.x * 32, d0 = blockIdx.y * 32;
    int tx = threadIdx.x, ty = threadIdx.y;
    const float* src = g_V + (size_t)bh * SDIM * HDIM;
#pragma unroll
    for (int r = 0; r < 4; r++)
        T[ty + 8 * r][tx] = src[(size_t)(s0 + ty + 8 * r) * HDIM + d0 + tx];
    __syncthreads();
#pragma unroll
    for (int r = 0; r < 4; r++) {
        int d = d0 + ty + 8 * r;
        float v = T[tx][ty + 8 * r];
        __nv_bfloat16 h, lo;
        split_bf16(v, h, lo);
        size_t o = ((size_t)bh * HDIM + d) * SDIM + s0 + tx;
        g_Vth[o] = h;
        g_Vtl[o] = lo;
    }
}

// ---------------- warp-mma bf16 hi/lo GEMM (cp.async + ldmatrix) -------------
// fused=1: C(4096x3072) = x @ [Wq|Wk|Wv] (dest Q/K/V per 1024-col group)
// fused=0: C(4096x1024) = WV @ Wo -> Cext
#define LDW 40
#define GT_TILE (128*LDW)          // elements per 128x32 tile
#define GT_STAGE (4*GT_TILE)       // Ah, Al, Bh, Bl
#define GEMM_SMEM (2*GT_STAGE*2)   // bytes (2 stages, bf16) = 81920
#define NCHUNK 32                  // K=1024 / 32

__global__ void __launch_bounds__(256, 2)
gemm_mma(const float* __restrict__ bq, const float* __restrict__ bv,
         const float* __restrict__ bo, float* __restrict__ Cext, int fused)
{
    extern __shared__ __nv_bfloat16 dynsm[];

    int tid = threadIdx.x;
    int wid = tid >> 5, l = tid & 31;
    int wm = wid >> 2, wn = wid & 3;
    int mw0 = wm * 64, nw0 = wn * 32;
    int m0 = blockIdx.y * 128;
    int n0g = blockIdx.x * 128;                 // global col (fused: 0..3071)
    int j = fused ? (n0g >> 10) : 3;            // 0=Q 1=K 2=V 3=out
    int gr = l >> 2, kc = (l & 3) * 2;

    const __nv_bfloat16* A_h = fused ? g_xh : g_WVh;
    const __nv_bfloat16* A_l = fused ? g_xl : g_WVl;
    size_t brow = (size_t)(fused ? n0g : 3 * NSTATE + n0g) * NSTATE;
    const __nv_bfloat16* srcs[4] = { A_h, A_l, g_Wth + brow, g_Wtl + brow };
    int rb[4] = { m0, m0, 0, 0 };

    // per-lane ldmatrix address components
    int aRowIn = (l & 7) + ((l >> 3) & 1) * 8;
    int aColSel = (l >> 4) * 8;
    uint32_t aoff = (uint32_t)(((mw0 + aRowIn) * LDW + aColSel) * 2);
    int bRowIn = (l & 7) + (l >> 4) * 8;
    int bColSel = ((l >> 3) & 1) * 8;
    uint32_t boff = (uint32_t)(((nw0 + bRowIn) * LDW + bColSel) * 2);
    uint32_t smemBase = (uint32_t)__cvta_generic_to_shared(dynsm);

    float c[4][4][4];
#pragma unroll
    for (int mt = 0; mt < 4; mt++)
#pragma unroll
        for (int nt = 0; nt < 4; nt++)
#pragma unroll
            for (int e = 0; e < 4; e++) c[mt][nt][e] = 0.f;

    auto loadStage = [&](int chunk, int p) {
        int k0 = chunk * 32;
        __nv_bfloat16* st = dynsm + p * GT_STAGE;
#pragma unroll
        for (int i = 0; i < 8; i++) {
            int idx = tid + i * 256;
            int t = idx >> 9, e = idx & 511;
            int row = e >> 2, seg = e & 3;
            cp16(st + t * GT_TILE + row * LDW + seg * 8,
                 srcs[t] + (size_t)(rb[t] + row) * NSTATE + k0 + seg * 8);
        }
    };

    loadStage(0, 0);
    CP_COMMIT();

    for (int it = 0; it < NCHUNK; it++) {
        int p = it & 1;
        if (it + 1 < NCHUNK) {
            loadStage(it + 1, p ^ 1);
            CP_COMMIT();
            CP_WAIT(1);
        } else {
            CP_WAIT(0);
        }
        __syncthreads();

        uint32_t sb = smemBase + p * (GT_STAGE * 2);
#pragma unroll
        for (int kk = 0; kk < 32; kk += 16) {
            uint32_t bh[4][2], bl[4][2];
#pragma unroll
            for (int np = 0; np < 2; np++) {
                uint32_t stepB = (uint32_t)((np * 16 * LDW + kk) * 2);
                uint32_t r[4];
                ldsm4(r, sb + 2 * GT_TILE * 2 + boff + stepB);
                bh[np * 2][0] = r[0]; bh[np * 2][1] = r[1];
                bh[np * 2 + 1][0] = r[2]; bh[np * 2 + 1][1] = r[3];
                ldsm4(r, sb + 3 * GT_TILE * 2 + boff + stepB);
                bl[np * 2][0] = r[0]; bl[np * 2][1] = r[1];
                bl[np * 2 + 1][0] = r[2]; bl[np * 2 + 1][1] = r[3];
            }
#pragma unroll
            for (int mt = 0; mt < 4; mt++) {
                uint32_t stepA = (uint32_t)((mt * 16 * LDW + kk) * 2);
                uint32_t ah[4], al[4];
                ldsm4(ah, sb + aoff + stepA);
                ldsm4(al, sb + GT_TILE * 2 + aoff + stepA);
#pragma unroll
                for (int nt = 0; nt < 4; nt++) mma16816(c[mt][nt], ah, bh[nt]);
#pragma unroll
                for (int nt = 0; nt < 4; nt++) mma16816(c[mt][nt], ah, bl[nt]);
#pragma unroll
                for (int nt = 0; nt < 4; nt++) mma16816(c[mt][nt], al, bh[nt]);
            }
        }
        __syncthreads();
    }

    // epilogue
    float scl = (j < 2) ? SCALE_QK : 1.0f;
#pragma unroll
    for (int mt = 0; mt < 4; mt++) {
#pragma unroll
        for (int nt = 0; nt < 4; nt++) {
            int ncol = n0g + nw0 + nt * 8 + kc;
            int nn = ncol & (NSTATE - 1);
            float b0 = 0.f, b1 = 0.f;
            if (j == 0)      { b0 = bq[nn]; b1 = bq[nn + 1]; }
            else if (j == 2) { b0 = bv[nn]; b1 = bv[nn + 1]; }
            else if (j == 3) { b0 = bo[nn]; b1 = bo[nn + 1]; }
#pragma unroll
            for (int half = 0; half < 2; half++) {
                int m = m0 + mw0 + mt * 16 + gr + half * 8;
                float v0 = (c[mt][nt][half * 2 + 0] + b0) * scl;
                float v1 = (c[mt][nt][half * 2 + 1] + b1) * scl;
                if (j == 3) {
                    *(float2*)(Cext + (size_t)m * NSTATE + nn) = make_float2(v0, v1);
                } else {
                    int b = m >> 11, s = m & (SDIM - 1);
                    int h2 = nn >> 6, d = nn & (HDIM - 1);
                    size_t o = ((size_t)(b * NHEAD + h2) * SDIM + s) * HDIM + d;
                    if (j == 2) {
                        *(float2*)(g_V + o) = make_float2(v0, v1);
                    } else {
                        uint32_t uh, ul;
                        packsplit2(v0, v1, uh, ul);
                        __nv_bfloat16* dh = j ? g_Kh : g_Qh;
                        __nv_bfloat16* dl = j ? g_Kl : g_Ql;
                        *(uint32_t*)&dh[o] = uh;
                        *(uint32_t*)&dl[o] = ul;
                    }
                }
            }
        }
    }
}

// ---------------- tensor-core flash attention (cp.async + ldmatrix) ---------
// Also writes the fully-masked region of qk (-1e9) — fill_mask is absorbed.
// Writes WV directly as bf16 hi/lo (convert_wv is absorbed).
#define LDK 72
#define KV_TILE (64*LDK)                 // one 64-row tile
#define KV_STAGE (4*KV_TILE)             // Kh, Kl, Vh, Vl
#define FLASH_SMEM ((128*2*LDK + 2*KV_STAGE) * 2)   // 110592 bytes

__global__ void __launch_bounds__(256, 2)
flash_mma(float* __restrict__ qk_out)
{
    extern __shared__ __nv_bfloat16 sm[];
    __nv_bfloat16* Qh = sm;
    __nv_bfloat16* Ql = Qh + 128 * LDK;
    __nv_bfloat16* KV = Ql + 128 * LDK;   // 2 stages x [Kh|Kl|Vh|Vl]

    int qb = gridDim.x - 1 - blockIdx.x;    // big tiles first
    int hh = blockIdx.y, b = blockIdx.z;
    int bh = b * NHEAD + hh;
    int q0 = qb * 128;
    int tid = threadIdx.x, w = tid >> 5, l = tid & 31;
    int gr = l >> 2, kc = (l & 3) * 2;
    int q0w = q0 + w * 16;

    const __nv_bfloat16* Qhg = g_Qh + (size_t)bh * SDIM * HDIM;
    const __nv_bfloat16* Qlg = g_Ql + (size_t)bh * SDIM * HDIM;
    const __nv_bfloat16* Khg = g_Kh + (size_t)bh * SDIM * HDIM;
    const __nv_bfloat16* Klg = g_Kl + (size_t)bh * SDIM * HDIM;
    const __nv_bfloat16* Vhg = g_Vth + (size_t)bh * HDIM * SDIM;
    const __nv_bfloat16* Vlg = g_Vtl + (size_t)bh * HDIM * SDIM;

    // Q block [128][64] hi/lo (plain loads; one-time)
#pragma unroll
    for (int i = 0; i < 4; i++) {
        int e = tid + i * 256;
        int row = e >> 3, col = (e & 7) * 8;
        *(uint4*)&Qh[row * LDK + col] = *(const uint4*)(Qhg + (size_t)(q0 + row) * HDIM + col);
        *(uint4*)&Ql[row * LDK + col] = *(const uint4*)(Qlg + (size_t)(q0 + row) * HDIM + col);
    }

    auto loadKV = [&](int t, int p) {
        int k0 = t * 64;
        __nv_bfloat16* st = KV + p * KV_STAGE;
#pragma unroll
        for (int i = 0; i < 8; i++) {
            int idx = tid + i * 256;               // 0..2047
            int arr = idx >> 9;                    // 0..3
            int e = idx & 511;
            int row = e >> 3, seg = e & 7;
            const __nv_bfloat16* src;
            if (arr == 0)      src = Khg + (size_t)(k0 + row) * HDIM + seg * 8;
            else if (arr == 1) src = Klg + (size_t)(k0 + row) * HDIM + seg * 8;
            else if (arr == 2) src = Vhg + (size_t)row * SDIM + k0 + seg * 8;
            else               src = Vlg + (size_t)row * SDIM + k0 + seg * 8;
            cp16(st + arr * KV_TILE + row * LDK + seg * 8, src);
        }
    };

    int nT = qb * 2 + 2;
    loadKV(0, 0);
    CP_COMMIT();

    // ---- absorbed causal fill: this warp's rows, cols [kfillw, SDIM) ----
    {
        int kfillw = ((q0w + 16 + 63) >> 6) << 6;
        float4 neg4 = make_float4(-1e9f, -1e9f, -1e9f, -1e9f);
#pragma unroll 1
        for (int r = 0; r < 16; r++) {
            float* base = qk_out + ((size_t)bh * SDIM + q0w + r) * SDIM;
            for (int c4 = (kfillw >> 2) + l; c4 < (SDIM >> 2); c4 += 32)
                *(float4*)(base + c4 * 4) = neg4;
        }
    }

    // ldmatrix lane address components
    uint32_t smemU = (uint32_t)__cvta_generic_to_shared(sm);
    int aRowIn = (l & 7) + ((l >> 3) & 1) * 8;
    int aColSel = (l >> 4) * 8;
    uint32_t aoff = (uint32_t)(((w * 16 + aRowIn) * LDK + aColSel) * 2);
    int bRowIn = (l & 7) + (l >> 4) * 8;
    int bColSel = ((l >> 3) & 1) * 8;
    uint32_t boff = (uint32_t)((bRowIn * LDK + bColSel) * 2);
    uint32_t qhB = smemU + aoff;
    uint32_t qlB = smemU + 128 * LDK * 2 + aoff;
    uint32_t kvB = smemU + 256 * LDK * 2;

    float oacc[8][4];
#pragma unroll
    for (int nd = 0; nd < 8; nd++)
#pragma unroll
        for (int e = 0; e < 4; e++) oacc[nd][e] = 0.f;
    float mrow[2] = {-INFINITY, -INFINITY};
    float lrow[2] = {0.f, 0.f};

    for (int t = 0; t < nT; t++) {
        int p = t & 1;
        int k0 = t * 64;
        if (t + 1 < nT) {
            loadKV(t + 1, p ^ 1);
            CP_COMMIT();
            CP_WAIT(1);
        } else {
            CP_WAIT(0);
        }
        __syncthreads();

        if (k0 <= q0w + 15) {
            uint32_t bKh = kvB + (p * KV_STAGE + 0 * KV_TILE) * 2 + boff;
            uint32_t bKl = kvB + (p * KV_STAGE + 1 * KV_TILE) * 2 + boff;
            uint32_t bVh = kvB + (p * KV_STAGE + 2 * KV_TILE) * 2 + boff;
            uint32_t bVl = kvB + (p * KV_STAGE + 3 * KV_TILE) * 2 + boff;

            float sacc[8][4];
#pragma unroll
            for (int nt = 0; nt < 8; nt++)
#pragma unroll
                for (int e = 0; e < 4; e++) sacc[nt][e] = 0.f;

            // ---- S = Q K^T ----
#pragma unroll
            for (int kk = 0; kk < 4; kk++) {
                uint32_t stepQ = (uint32_t)(kk * 16 * 2);
                uint32_t ah[4], al[4];
                ldsm4(ah, qhB + stepQ);
                ldsm4(al, qlB + stepQ);
#pragma unroll
                for (int jj = 0; jj < 4; jj++) {
                    uint32_t stepB = (uint32_t)((jj * 16 * LDK + kk * 16) * 2);
                    uint32_t rh[4], rl[4];
                    ldsm4(rh, bKh + stepB);
                    ldsm4(rl, bKl + stepB);
                    mma2(sacc[2 * jj], sacc[2 * jj + 1], ah, rh);
                    mma2(sacc[2 * jj], sacc[2 * jj + 1], ah, rl);
                    mma2(sacc[2 * jj], sacc[2 * jj + 1], al, rh);
                }
            }

            if (k0 + 63 > q0w) {
#pragma unroll
                for (int nt = 0; nt < 8; nt++)
#pragma unroll
                    for (int e = 0; e < 4; e++) {
                        int kg = k0 + nt * 8 + kc + (e & 1);
                        int qg = q0w + gr + ((e >> 1) ? 8 : 0);
                        if (kg > qg) sacc[nt][e] = -1e9f;
                    }
            }

            float* qp = qk_out + ((size_t)bh * SDIM + q0w + gr) * SDIM + k0;
#pragma unroll
            for (int nt = 0; nt < 8; nt++) {
                *(float2*)(qp + nt * 8 + kc) = make_float2(sacc[nt][0], sacc[nt][1]);
                *(float2*)(qp + 8 * SDIM + nt * 8 + kc) = make_float2(sacc[nt][2], sacc[nt][3]);
            }

            // ---- online softmax ----
#pragma unroll
            for (int half = 0; half < 2; half++) {
                int e0 = half * 2;
                float tmax = -INFINITY;
#pragma unroll
                for (int nt = 0; nt < 8; nt++)
                    tmax = fmaxf(tmax, fmaxf(sacc[nt][e0], sacc[nt][e0 + 1]));
                tmax = fmaxf(tmax, __shfl_xor_sync(0xffffffffu, tmax, 1));
                tmax = fmaxf(tmax, __shfl_xor_sync(0xffffffffu, tmax, 2));
                float mnew = fmaxf(mrow[half], tmax);
                float fac = __expf(mrow[half] - mnew);
                mrow[half] = mnew;
                float ps = 0.f;
#pragma unroll
                for (int nt = 0; nt < 8; nt++) {
                    float p0 = __expf(sacc[nt][e0] - mnew);
                    float p1 = __expf(sacc[nt][e0 + 1] - mnew);
                    sacc[nt][e0] = p0; sacc[nt][e0 + 1] = p1;
                    ps += p0 + p1;
                }
                lrow[half] = lrow[half] * fac + ps;
#pragma unroll
                for (int nd = 0; nd < 8; nd++) {
                    oacc[nd][e0] *= fac;
                    oacc[nd][e0 + 1] *= fac;
                }
            }

            // ---- O += P V ----
#pragma unroll
            for (int kk = 0; kk < 4; kk++) {
                uint32_t ph[4], pl[4];
                packsplit2(sacc[2 * kk][0],     sacc[2 * kk][1],     ph[0], pl[0]);
                packsplit2(sacc[2 * kk][2],     sacc[2 * kk][3],     ph[1], pl[1]);
                packsplit2(sacc[2 * kk + 1][0], sacc[2 * kk + 1][1], ph[2], pl[2]);
                packsplit2(sacc[2 * kk + 1][2], sacc[2 * kk + 1][3], ph[3], pl[3]);
#pragma unroll
                for (int jj = 0; jj < 4; jj++) {
                    uint32_t stepB = (uint32_t)((jj * 16 * LDK + kk * 16) * 2);
                    uint32_t rh[4], rl[4];
                    ldsm4(rh, bVh + stepB);
                    ldsm4(rl, bVl + stepB);
                    mma2(oacc[2 * jj], oacc[2 * jj + 1], ph, rh);
                    mma2(oacc[2 * jj], oacc[2 * jj + 1], ph, rl);
                    mma2(oacc[2 * jj], oacc[2 * jj + 1], pl, rh);
                }
            }
        }
        __syncthreads();
    }

#pragma unroll
    for (int half = 0; half < 2; half++) {
        lrow[half] += __shfl_xor_sync(0xffffffffu, lrow[half], 1);
        lrow[half] += __shfl_xor_sync(0xffffffffu, lrow[half], 2);
    }
    float inv0 = 1.f / lrow[0], inv1 = 1.f / lrow[1];
    // direct bf16 hi/lo WV output (bit-identical to post-hoc convert_wv split)
#pragma unroll
    for (int nd = 0; nd < 8; nd++) {
        int d = nd * 8 + kc;
        int q = q0w + gr;
        size_t o0 = ((size_t)(b * SDIM + q) * NHEAD + hh) * HDIM + d;
        size_t o1 = ((size_t)(b * SDIM + q + 8) * NHEAD + hh) * HDIM + d;
        uint32_t uh, ul;
        packsplit2(oacc[nd][0] * inv0, oacc[nd][1] * inv0, uh, ul);
        *(uint32_t*)&g_WVh[o0] = uh;
        *(uint32_t*)&g_WVl[o0] = ul;
        packsplit2(oacc[nd][2] * inv1, oacc[nd][3] * inv1, uh, ul);
        *(uint32_t*)&g_WVh[o1] = uh;
        *(uint32_t*)&g_WVl[o1] = ul;
    }
}

// ---------------------------------------------------------------------------
extern "C" void kernel_launch(void* const* d_in, const int* in_sizes, int n_in,
                              void* d_out, int out_size)
{
    const float* x  = (const float*)d_in[0];
    const float* Wq = (const float*)d_in[2];
    const float* bq = (const float*)d_in[3];
    const float* Wk = (const float*)d_in[4];
    const float* Wv = (const float*)d_in[5];
    const float* bv = (const float*)d_in[6];
    const float* Wo = (const float*)d_in[7];
    const float* bo = (const float*)d_in[8];

    float* out = (float*)d_out;                       // [b,s,1024]
    float* qk  = out + (size_t)BDIM * SDIM * NSTATE;  // [b,h,s,s]

    static bool attr_set = false;
    if (!attr_set) {
        cudaFuncSetAttribute(flash_mma, cudaFuncAttributeMaxDynamicSharedMemorySize, FLASH_SMEM);
        cudaFuncSetAttribute(gemm_mma, cudaFuncAttributeMaxDynamicSharedMemorySize, GEMM_SMEM);
        attr_set = true;
    }

    convert_x_kernel<<<MROWS * NSTATE / 4 / 256, 256>>>(x);
    transpose_convert<<<dim3(32, 32, 4), dim3(32, 8)>>>(Wq, Wk, Wv, Wo);

    // fused QKV projection: N = 3072
    gemm_mma<<<dim3(24, 32), 256, GEMM_SMEM>>>(bq, bv, nullptr, nullptr, 1);

    vtrans<<<dim3(SDIM / 32, HDIM / 32, BDIM * NHEAD), dim3(32, 8)>>>();

    flash_mma<<<dim3(SDIM / 128, NHEAD, BDIM), 256, FLASH_SMEM>>>(qk);

    gemm_mma<<<dim3(8, 32), 256, GEMM_SMEM>>>(nullptr, nullptr, bo, out, 0);
}

// round 15
// speedup vs baseline: 1.0483x; 1.0483x over previous
#include <cuda_runtime.h>
#include <cuda_bf16.h>
#include <math.h>
#include <cstdint>

#define BDIM   2
#define SDIM   2048
#define NSTATE 1024
#define NHEAD  16
#define HDIM   64
#define MROWS  (BDIM*SDIM)            // 4096

constexpr float SCALE_QK = 0.35355339059327373f;  // 64^-0.25

// ---------------- scratch (static device globals; no allocs allowed) --------
__device__ float g_V [BDIM*NHEAD*SDIM*HDIM];   // [b][h][s][d] fp32

__device__ __nv_bfloat16 g_Qh[BDIM*NHEAD*SDIM*HDIM];  // [b][h][s][d] hi/lo, pre-scaled
__device__ __nv_bfloat16 g_Ql[BDIM*NHEAD*SDIM*HDIM];
__device__ __nv_bfloat16 g_Kh[BDIM*NHEAD*SDIM*HDIM];
__device__ __nv_bfloat16 g_Kl[BDIM*NHEAD*SDIM*HDIM];
__device__ __nv_bfloat16 g_Vth[BDIM*NHEAD*HDIM*SDIM]; // [b][h][d][s] hi/lo
__device__ __nv_bfloat16 g_Vtl[BDIM*NHEAD*HDIM*SDIM];

__device__ __nv_bfloat16 g_xh [MROWS*NSTATE];
__device__ __nv_bfloat16 g_xl [MROWS*NSTATE];
__device__ __nv_bfloat16 g_WVh[MROWS*NSTATE];         // written directly by flash
__device__ __nv_bfloat16 g_WVl[MROWS*NSTATE];
__device__ __nv_bfloat16 g_Wth[4*NSTATE*NSTATE];  // transposed weights [n][k]; q,k,v,o contiguous
__device__ __nv_bfloat16 g_Wtl[4*NSTATE*NSTATE];

// ---------------- helpers ---------------------------------------------------
__device__ __forceinline__ void split_bf16(float v, __nv_bfloat16& h, __nv_bfloat16& l) {
    h = __float2bfloat16_rn(v);
    l = __float2bfloat16_rn(v - __bfloat162float(h));
}
__device__ __forceinline__ void packsplit2(float x, float y, uint32_t& hh, uint32_t& ll) {
    __nv_bfloat16 xh, xl, yh, yl;
    split_bf16(x, xh, xl); split_bf16(y, yh, yl);
    __nv_bfloat162 hv, lv;
    hv.x = xh; hv.y = yh; lv.x = xl; lv.y = yl;
    hh = *(uint32_t*)&hv; ll = *(uint32_t*)&lv;
}
__device__ __forceinline__ void mma16816(float* c, const uint32_t* a, const uint32_t* b) {
    asm volatile(
        "mma.sync.aligned.m16n8k16.row.col.f32.bf16.bf16.f32 "
        "{%0,%1,%2,%3}, {%4,%5,%6,%7}, {%8,%9}, {%0,%1,%2,%3};"
        : "+f"(c[0]), "+f"(c[1]), "+f"(c[2]), "+f"(c[3])
        : "r"(a[0]), "r"(a[1]), "r"(a[2]), "r"(a[3]), "r"(b[0]), "r"(b[1]));
}
__device__ __forceinline__ void mma2(float* c0, float* c1, const uint32_t* a, const uint32_t* r4) {
    mma16816(c0, a, r4);
    mma16816(c1, a, r4 + 2);
}
__device__ __forceinline__ void ldsm4(uint32_t* r, uint32_t saddr) {
    asm volatile("ldmatrix.sync.aligned.m8n8.x4.shared.b16 {%0,%1,%2,%3}, [%4];"
        : "=r"(r[0]), "=r"(r[1]), "=r"(r[2]), "=r"(r[3]) : "r"(saddr));
}
__device__ __forceinline__ void cp16(void* smem_dst, const void* gsrc) {
    uint32_t s = (uint32_t)__cvta_generic_to_shared(smem_dst);
    asm volatile("cp.async.ca.shared.global [%0], [%1], 16;" :: "r"(s), "l"(gsrc) : "memory");
}
#define CP_COMMIT() asm volatile("cp.async.commit_group;" ::: "memory")
#define CP_WAIT(n)  asm volatile("cp.async.wait_group %0;" :: "n"(n) : "memory")

// ---------------- conversion kernels ----------------------------------------
__global__ void convert_x_kernel(const float* __restrict__ x) {
    size_t i = (size_t)blockIdx.x * 256 + threadIdx.x;
    float4 v = ((const float4*)x)[i];
    __nv_bfloat16 h[4], l[4];
    split_bf16(v.x, h[0], l[0]); split_bf16(v.y, h[1], l[1]);
    split_bf16(v.z, h[2], l[2]); split_bf16(v.w, h[3], l[3]);
    ((uint2*)g_xh)[i] = *(uint2*)h;
    ((uint2*)g_xl)[i] = *(uint2*)l;
}

__global__ void transpose_convert(const float* __restrict__ W0, const float* __restrict__ W1,
                                  const float* __restrict__ W2, const float* __restrict__ W3) {
    __shared__ float T[32][33];
    int w = blockIdx.z;
    const float* W = (w == 0) ? W0 : (w == 1) ? W1 : (w == 2) ? W2 : W3;
    int n0 = blockIdx.x * 32, k0 = blockIdx.y * 32;
    int tx = threadIdx.x, ty = threadIdx.y;
#pragma unroll
    for (int r = 0; r < 4; r++) {
        int kl = ty + 8 * r;
        T[kl][tx] = W[(size_t)(k0 + kl) * NSTATE + n0 + tx];
    }
    __syncthreads();
    size_t base = (size_t)w * NSTATE * NSTATE;
#pragma unroll
    for (int r = 0; r < 4; r++) {
        int nl = ty + 8 * r;
        float v = T[tx][nl];
        __nv_bfloat16 h, l;
        split_bf16(v, h, l);
        size_t o = base + (size_t)(n0 + nl) * NSTATE + k0 + tx;
        g_Wth[o] = h;
        g_Wtl[o] = l;
    }
}

// V transpose: g_V[b,h,s,d] fp32 -> g_Vt{h,l}[b,h,d,s] bf16
__global__ void vtrans() {
    __shared__ float T[32][33];
    int bh = blockIdx.z;
    int s0 = blockIdx.x * 32, d0 = blockIdx.y * 32;
    int tx = threadIdx.x, ty = threadIdx.y;
    const float* src = g_V + (size_t)bh * SDIM * HDIM;
#pragma unroll
    for (int r = 0; r < 4; r++)
        T[ty + 8 * r][tx] = src[(size_t)(s0 + ty + 8 * r) * HDIM + d0 + tx];
    __syncthreads();
#pragma unroll
    for (int r = 0; r < 4; r++) {
        int d = d0 + ty + 8 * r;
        float v = T[tx][ty + 8 * r];
        __nv_bfloat16 h, lo;
        split_bf16(v, h, lo);
        size_t o = ((size_t)bh * HDIM + d) * SDIM + s0 + tx;
        g_Vth[o] = h;
        g_Vtl[o] = lo;
    }
}

// ---------------- warp-mma bf16 hi/lo GEMM (cp.async + ldmatrix) -------------
// fused=1: C(4096x3072) = x @ [Wq|Wk|Wv] (dest Q/K/V per 1024-col group)
// fused=0: C(4096x1024) = WV @ Wo -> Cext
#define LDW 40
#define GT_TILE (128*LDW)          // elements per 128x32 tile
#define GT_STAGE (4*GT_TILE)       // Ah, Al, Bh, Bl
#define GEMM_SMEM (2*GT_STAGE*2)   // bytes (2 stages, bf16) = 81920
#define NCHUNK 32                  // K=1024 / 32

__global__ void __launch_bounds__(256, 2)
gemm_mma(const float* __restrict__ bq, const float* __restrict__ bv,
         const float* __restrict__ bo, float* __restrict__ Cext, int fused)
{
    extern __shared__ __nv_bfloat16 dynsm[];

    int tid = threadIdx.x;
    int wid = tid >> 5, l = tid & 31;
    int wm = wid >> 2, wn = wid & 3;
    int mw0 = wm * 64, nw0 = wn * 32;
    int m0 = blockIdx.y * 128;
    int n0g = blockIdx.x * 128;                 // global col (fused: 0..3071)
    int j = fused ? (n0g >> 10) : 3;            // 0=Q 1=K 2=V 3=out
    int gr = l >> 2, kc = (l & 3) * 2;

    const __nv_bfloat16* A_h = fused ? g_xh : g_WVh;
    const __nv_bfloat16* A_l = fused ? g_xl : g_WVl;
    size_t brow = (size_t)(fused ? n0g : 3 * NSTATE + n0g) * NSTATE;
    const __nv_bfloat16* srcs[4] = { A_h, A_l, g_Wth + brow, g_Wtl + brow };
    int rb[4] = { m0, m0, 0, 0 };

    // per-lane ldmatrix address components
    int aRowIn = (l & 7) + ((l >> 3) & 1) * 8;
    int aColSel = (l >> 4) * 8;
    uint32_t aoff = (uint32_t)(((mw0 + aRowIn) * LDW + aColSel) * 2);
    int bRowIn = (l & 7) + (l >> 4) * 8;
    int bColSel = ((l >> 3) & 1) * 8;
    uint32_t boff = (uint32_t)(((nw0 + bRowIn) * LDW + bColSel) * 2);
    uint32_t smemBase = (uint32_t)__cvta_generic_to_shared(dynsm);

    float c[4][4][4];
#pragma unroll
    for (int mt = 0; mt < 4; mt++)
#pragma unroll
        for (int nt = 0; nt < 4; nt++)
#pragma unroll
            for (int e = 0; e < 4; e++) c[mt][nt][e] = 0.f;

    auto loadStage = [&](int chunk, int p) {
        int k0 = chunk * 32;
        __nv_bfloat16* st = dynsm + p * GT_STAGE;
#pragma unroll
        for (int i = 0; i < 8; i++) {
            int idx = tid + i * 256;
            int t = idx >> 9, e = idx & 511;
            int row = e >> 2, seg = e & 3;
            cp16(st + t * GT_TILE + row * LDW + seg * 8,
                 srcs[t] + (size_t)(rb[t] + row) * NSTATE + k0 + seg * 8);
        }
    };

    loadStage(0, 0);
    CP_COMMIT();

    for (int it = 0; it < NCHUNK; it++) {
        int p = it & 1;
        if (it + 1 < NCHUNK) {
            loadStage(it + 1, p ^ 1);
            CP_COMMIT();
            CP_WAIT(1);
        } else {
            CP_WAIT(0);
        }
        __syncthreads();

        uint32_t sb = smemBase + p * (GT_STAGE * 2);
#pragma unroll
        for (int kk = 0; kk < 32; kk += 16) {
            uint32_t bh[4][2], bl[4][2];
#pragma unroll
            for (int np = 0; np < 2; np++) {
                uint32_t stepB = (uint32_t)((np * 16 * LDW + kk) * 2);
                uint32_t r[4];
                ldsm4(r, sb + 2 * GT_TILE * 2 + boff + stepB);
                bh[np * 2][0] = r[0]; bh[np * 2][1] = r[1];
                bh[np * 2 + 1][0] = r[2]; bh[np * 2 + 1][1] = r[3];
                ldsm4(r, sb + 3 * GT_TILE * 2 + boff + stepB);
                bl[np * 2][0] = r[0]; bl[np * 2][1] = r[1];
                bl[np * 2 + 1][0] = r[2]; bl[np * 2 + 1][1] = r[3];
            }
#pragma unroll
            for (int mt = 0; mt < 4; mt++) {
                uint32_t stepA = (uint32_t)((mt * 16 * LDW + kk) * 2);
                uint32_t ah[4], al[4];
                ldsm4(ah, sb + aoff + stepA);
                ldsm4(al, sb + GT_TILE * 2 + aoff + stepA);
#pragma unroll
                for (int nt = 0; nt < 4; nt++) mma16816(c[mt][nt], ah, bh[nt]);
#pragma unroll
                for (int nt = 0; nt < 4; nt++) mma16816(c[mt][nt], ah, bl[nt]);
#pragma unroll
                for (int nt = 0; nt < 4; nt++) mma16816(c[mt][nt], al, bh[nt]);
            }
        }
        __syncthreads();
    }

    // epilogue
    float scl = (j < 2) ? SCALE_QK : 1.0f;
#pragma unroll
    for (int mt = 0; mt < 4; mt++) {
#pragma unroll
        for (int nt = 0; nt < 4; nt++) {
            int ncol = n0g + nw0 + nt * 8 + kc;
            int nn = ncol & (NSTATE - 1);
            float b0 = 0.f, b1 = 0.f;
            if (j == 0)      { b0 = bq[nn]; b1 = bq[nn + 1]; }
            else if (j == 2) { b0 = bv[nn]; b1 = bv[nn + 1]; }
            else if (j == 3) { b0 = bo[nn]; b1 = bo[nn + 1]; }
#pragma unroll
            for (int half = 0; half < 2; half++) {
                int m = m0 + mw0 + mt * 16 + gr + half * 8;
                float v0 = (c[mt][nt][half * 2 + 0] + b0) * scl;
                float v1 = (c[mt][nt][half * 2 + 1] + b1) * scl;
                if (j == 3) {
                    *(float2*)(Cext + (size_t)m * NSTATE + nn) = make_float2(v0, v1);
                } else {
                    int b = m >> 11, s = m & (SDIM - 1);
                    int h2 = nn >> 6, d = nn & (HDIM - 1);
                    size_t o = ((size_t)(b * NHEAD + h2) * SDIM + s) * HDIM + d;
                    if (j == 2) {
                        *(float2*)(g_V + o) = make_float2(v0, v1);
                    } else {
                        uint32_t uh, ul;
                        packsplit2(v0, v1, uh, ul);
                        __nv_bfloat16* dh = j ? g_Kh : g_Qh;
                        __nv_bfloat16* dl = j ? g_Kl : g_Ql;
                        *(uint32_t*)&dh[o] = uh;
                        *(uint32_t*)&dl[o] = ul;
                    }
                }
            }
        }
    }
}

// ---------------- tensor-core flash attention (cp.async + ldmatrix) ---------
// Also writes the fully-masked region of qk (-1e9) — fill_mask is absorbed.
// Writes WV directly as bf16 hi/lo (convert_wv is absorbed).
#define LDK 72
#define KV_TILE (64*LDK)                 // one 64-row tile
#define KV_STAGE (4*KV_TILE)             // Kh, Kl, Vh, Vl
#define FLASH_SMEM ((128*2*LDK + 2*KV_STAGE) * 2)   // 110592 bytes

__global__ __launch_bounds__(256)
void flash_mma(float* __restrict__ qk_out)
{
    extern __shared__ __nv_bfloat16 sm[];
    __nv_bfloat16* Qh = sm;
    __nv_bfloat16* Ql = Qh + 128 * LDK;
    __nv_bfloat16* KV = Ql + 128 * LDK;   // 2 stages x [Kh|Kl|Vh|Vl]

    int qb = gridDim.x - 1 - blockIdx.x;    // big tiles first
    int hh = blockIdx.y, b = blockIdx.z;
    int bh = b * NHEAD + hh;
    int q0 = qb * 128;
    int tid = threadIdx.x, w = tid >> 5, l = tid & 31;
    int gr = l >> 2, kc = (l & 3) * 2;
    int q0w = q0 + w * 16;

    const __nv_bfloat16* Qhg = g_Qh + (size_t)bh * SDIM * HDIM;
    const __nv_bfloat16* Qlg = g_Ql + (size_t)bh * SDIM * HDIM;
    const __nv_bfloat16* Khg = g_Kh + (size_t)bh * SDIM * HDIM;
    const __nv_bfloat16* Klg = g_Kl + (size_t)bh * SDIM * HDIM;
    const __nv_bfloat16* Vhg = g_Vth + (size_t)bh * HDIM * SDIM;
    const __nv_bfloat16* Vlg = g_Vtl + (size_t)bh * HDIM * SDIM;

    // Q block [128][64] hi/lo (plain loads; one-time)
#pragma unroll
    for (int i = 0; i < 4; i++) {
        int e = tid + i * 256;
        int row = e >> 3, col = (e & 7) * 8;
        *(uint4*)&Qh[row * LDK + col] = *(const uint4*)(Qhg + (size_t)(q0 + row) * HDIM + col);
        *(uint4*)&Ql[row * LDK + col] = *(const uint4*)(Qlg + (size_t)(q0 + row) * HDIM + col);
    }

    auto loadKV = [&](int t, int p) {
        int k0 = t * 64;
        __nv_bfloat16* st = KV + p * KV_STAGE;
#pragma unroll
        for (int i = 0; i < 8; i++) {
            int idx = tid + i * 256;               // 0..2047
            int arr = idx >> 9;                    // 0..3
            int e = idx & 511;
            int row = e >> 3, seg = e & 7;
            const __nv_bfloat16* src;
            if (arr == 0)      src = Khg + (size_t)(k0 + row) * HDIM + seg * 8;
            else if (arr == 1) src = Klg + (size_t)(k0 + row) * HDIM + seg * 8;
            else if (arr == 2) src = Vhg + (size_t)row * SDIM + k0 + seg * 8;
            else               src = Vlg + (size_t)row * SDIM + k0 + seg * 8;
            cp16(st + arr * KV_TILE + row * LDK + seg * 8, src);
        }
    };

    int nT = qb * 2 + 2;
    loadKV(0, 0);
    CP_COMMIT();

    // ---- absorbed causal fill: this warp's rows, cols [kfillw, SDIM) ----
    {
        int kfillw = ((q0w + 16 + 63) >> 6) << 6;
        float4 neg4 = make_float4(-1e9f, -1e9f, -1e9f, -1e9f);
#pragma unroll 1
        for (int r = 0; r < 16; r++) {
            float* base = qk_out + ((size_t)bh * SDIM + q0w + r) * SDIM;
            for (int c4 = (kfillw >> 2) + l; c4 < (SDIM >> 2); c4 += 32)
                *(float4*)(base + c4 * 4) = neg4;
        }
    }

    // ldmatrix lane address components
    uint32_t smemU = (uint32_t)__cvta_generic_to_shared(sm);
    int aRowIn = (l & 7) + ((l >> 3) & 1) * 8;
    int aColSel = (l >> 4) * 8;
    uint32_t aoff = (uint32_t)(((w * 16 + aRowIn) * LDK + aColSel) * 2);
    int bRowIn = (l & 7) + (l >> 4) * 8;
    int bColSel = ((l >> 3) & 1) * 8;
    uint32_t boff = (uint32_t)((bRowIn * LDK + bColSel) * 2);
    uint32_t qhB = smemU + aoff;
    uint32_t qlB = smemU + 128 * LDK * 2 + aoff;
    uint32_t kvB = smemU + 256 * LDK * 2;

    float oacc[8][4];
#pragma unroll
    for (int nd = 0; nd < 8; nd++)
#pragma unroll
        for (int e = 0; e < 4; e++) oacc[nd][e] = 0.f;
    float mrow[2] = {-INFINITY, -INFINITY};
    float lrow[2] = {0.f, 0.f};

    for (int t = 0; t < nT; t++) {
        int p = t & 1;
        int k0 = t * 64;
        if (t + 1 < nT) {
            loadKV(t + 1, p ^ 1);
            CP_COMMIT();
            CP_WAIT(1);
        } else {
            CP_WAIT(0);
        }
        __syncthreads();

        if (k0 <= q0w + 15) {
            uint32_t bKh = kvB + (p * KV_STAGE + 0 * KV_TILE) * 2 + boff;
            uint32_t bKl = kvB + (p * KV_STAGE + 1 * KV_TILE) * 2 + boff;
            uint32_t bVh = kvB + (p * KV_STAGE + 2 * KV_TILE) * 2 + boff;
            uint32_t bVl = kvB + (p * KV_STAGE + 3 * KV_TILE) * 2 + boff;

            float sacc[8][4];
#pragma unroll
            for (int nt = 0; nt < 8; nt++)
#pragma unroll
                for (int e = 0; e < 4; e++) sacc[nt][e] = 0.f;

            // ---- S = Q K^T ----
#pragma unroll
            for (int kk = 0; kk < 4; kk++) {
                uint32_t stepQ = (uint32_t)(kk * 16 * 2);
                uint32_t ah[4], al[4];
                ldsm4(ah, qhB + stepQ);
                ldsm4(al, qlB + stepQ);
#pragma unroll
                for (int jj = 0; jj < 4; jj++) {
                    uint32_t stepB = (uint32_t)((jj * 16 * LDK + kk * 16) * 2);
                    uint32_t rh[4], rl[4];
                    ldsm4(rh, bKh + stepB);
                    ldsm4(rl, bKl + stepB);
                    mma2(sacc[2 * jj], sacc[2 * jj + 1], ah, rh);
                    mma2(sacc[2 * jj], sacc[2 * jj + 1], ah, rl);
                    mma2(sacc[2 * jj], sacc[2 * jj + 1], al, rh);
                }
            }

            if (k0 + 63 > q0w) {
#pragma unroll
                for (int nt = 0; nt < 8; nt++)
#pragma unroll
                    for (int e = 0; e < 4; e++) {
                        int kg = k0 + nt * 8 + kc + (e & 1);
                        int qg = q0w + gr + ((e >> 1) ? 8 : 0);
                        if (kg > qg) sacc[nt][e] = -1e9f;
                    }
            }

            float* qp = qk_out + ((size_t)bh * SDIM + q0w + gr) * SDIM + k0;
#pragma unroll
            for (int nt = 0; nt < 8; nt++) {
                *(float2*)(qp + nt * 8 + kc) = make_float2(sacc[nt][0], sacc[nt][1]);
                *(float2*)(qp + 8 * SDIM + nt * 8 + kc) = make_float2(sacc[nt][2], sacc[nt][3]);
            }

            // ---- online softmax ----
#pragma unroll
            for (int half = 0; half < 2; half++) {
                int e0 = half * 2;
                float tmax = -INFINITY;
#pragma unroll
                for (int nt = 0; nt < 8; nt++)
                    tmax = fmaxf(tmax, fmaxf(sacc[nt][e0], sacc[nt][e0 + 1]));
                tmax = fmaxf(tmax, __shfl_xor_sync(0xffffffffu, tmax, 1));
                tmax = fmaxf(tmax, __shfl_xor_sync(0xffffffffu, tmax, 2));
                float mnew = fmaxf(mrow[half], tmax);
                float fac = __expf(mrow[half] - mnew);
                mrow[half] = mnew;
                float ps = 0.f;
#pragma unroll
                for (int nt = 0; nt < 8; nt++) {
                    float p0 = __expf(sacc[nt][e0] - mnew);
                    float p1 = __expf(sacc[nt][e0 + 1] - mnew);
                    sacc[nt][e0] = p0; sacc[nt][e0 + 1] = p1;
                    ps += p0 + p1;
                }
                lrow[half] = lrow[half] * fac + ps;
#pragma unroll
                for (int nd = 0; nd < 8; nd++) {
                    oacc[nd][e0] *= fac;
                    oacc[nd][e0 + 1] *= fac;
                }
            }

            // ---- O += P V ----
#pragma unroll
            for (int kk = 0; kk < 4; kk++) {
                uint32_t ph[4], pl[4];
                packsplit2(sacc[2 * kk][0],     sacc[2 * kk][1],     ph[0], pl[0]);
                packsplit2(sacc[2 * kk][2],     sacc[2 * kk][3],     ph[1], pl[1]);
                packsplit2(sacc[2 * kk + 1][0], sacc[2 * kk + 1][1], ph[2], pl[2]);
                packsplit2(sacc[2 * kk + 1][2], sacc[2 * kk + 1][3], ph[3], pl[3]);
#pragma unroll
                for (int jj = 0; jj < 4; jj++) {
                    uint32_t stepB = (uint32_t)((jj * 16 * LDK + kk * 16) * 2);
                    uint32_t rh[4], rl[4];
                    ldsm4(rh, bVh + stepB);
                    ldsm4(rl, bVl + stepB);
                    mma2(oacc[2 * jj], oacc[2 * jj + 1], ph, rh);
                    mma2(oacc[2 * jj], oacc[2 * jj + 1], ph, rl);
                    mma2(oacc[2 * jj], oacc[2 * jj + 1], pl, rh);
                }
            }
        }
        __syncthreads();
    }

#pragma unroll
    for (int half = 0; half < 2; half++) {
        lrow[half] += __shfl_xor_sync(0xffffffffu, lrow[half], 1);
        lrow[half] += __shfl_xor_sync(0xffffffffu, lrow[half], 2);
    }
    float inv0 = 1.f / lrow[0], inv1 = 1.f / lrow[1];
    // direct bf16 hi/lo WV output (bit-identical to post-hoc convert_wv split)
#pragma unroll
    for (int nd = 0; nd < 8; nd++) {
        int d = nd * 8 + kc;
        int q = q0w + gr;
        size_t o0 = ((size_t)(b * SDIM + q) * NHEAD + hh) * HDIM + d;
        size_t o1 = ((size_t)(b * SDIM + q + 8) * NHEAD + hh) * HDIM + d;
        uint32_t uh, ul;
        packsplit2(oacc[nd][0] * inv0, oacc[nd][1] * inv0, uh, ul);
        *(uint32_t*)&g_WVh[o0] = uh;
        *(uint32_t*)&g_WVl[o0] = ul;
        packsplit2(oacc[nd][2] * inv1, oacc[nd][3] * inv1, uh, ul);
        *(uint32_t*)&g_WVh[o1] = uh;
        *(uint32_t*)&g_WVl[o1] = ul;
    }
}

// ---------------------------------------------------------------------------
extern "C" void kernel_launch(void* const* d_in, const int* in_sizes, int n_in,
                              void* d_out, int out_size)
{
    const float* x  = (const float*)d_in[0];
    const float* Wq = (const float*)d_in[2];
    const float* bq = (const float*)d_in[3];
    const float* Wk = (const float*)d_in[4];
    const float* Wv = (const float*)d_in[5];
    const float* bv = (const float*)d_in[6];
    const float* Wo = (const float*)d_in[7];
    const float* bo = (const float*)d_in[8];

    float* out = (float*)d_out;                       // [b,s,1024]
    float* qk  = out + (size_t)BDIM * SDIM * NSTATE;  // [b,h,s,s]

    static bool attr_set = false;
    if (!attr_set) {
        cudaFuncSetAttribute(flash_mma, cudaFuncAttributeMaxDynamicSharedMemorySize, FLASH_SMEM);
        cudaFuncSetAttribute(gemm_mma, cudaFuncAttributeMaxDynamicSharedMemorySize, GEMM_SMEM);
        attr_set = true;
    }

    convert_x_kernel<<<MROWS * NSTATE / 4 / 256, 256>>>(x);
    transpose_convert<<<dim3(32, 32, 4), dim3(32, 8)>>>(Wq, Wk, Wv, Wo);

    // fused QKV projection: N = 3072
    gemm_mma<<<dim3(24, 32), 256, GEMM_SMEM>>>(bq, bv, nullptr, nullptr, 1);

    vtrans<<<dim3(SDIM / 32, HDIM / 32, BDIM * NHEAD), dim3(32, 8)>>>();

    flash_mma<<<dim3(SDIM / 128, NHEAD, BDIM), 256, FLASH_SMEM>>>(qk);

    gemm_mma<<<dim3(8, 32), 256, GEMM_SMEM>>>(nullptr, nullptr, bo, out, 0);
}

// round 16
// speedup vs baseline: 1.0668x; 1.0177x over previous
#include <cuda_runtime.h>
#include <cuda_bf16.h>
#include <math.h>
#include <cstdint>

#define BDIM   2
#define SDIM   2048
#define NSTATE 1024
#define NHEAD  16
#define HDIM   64
#define MROWS  (BDIM*SDIM)            // 4096

constexpr float SCALE_QK = 0.35355339059327373f;  // 64^-0.25

// ---------------- scratch (static device globals; no allocs allowed) --------
__device__ float g_V [BDIM*NHEAD*SDIM*HDIM];   // [b][h][s][d] fp32

__device__ __nv_bfloat16 g_Qh[BDIM*NHEAD*SDIM*HDIM];  // [b][h][s][d] hi/lo, pre-scaled
__device__ __nv_bfloat16 g_Ql[BDIM*NHEAD*SDIM*HDIM];
__device__ __nv_bfloat16 g_Kh[BDIM*NHEAD*SDIM*HDIM];
__device__ __nv_bfloat16 g_Kl[BDIM*NHEAD*SDIM*HDIM];
__device__ __nv_bfloat16 g_Vth[BDIM*NHEAD*HDIM*SDIM]; // [b][h][d][s] hi/lo
__device__ __nv_bfloat16 g_Vtl[BDIM*NHEAD*HDIM*SDIM];

__device__ __nv_bfloat16 g_xh [MROWS*NSTATE];
__device__ __nv_bfloat16 g_xl [MROWS*NSTATE];
__device__ __nv_bfloat16 g_WVh[MROWS*NSTATE];         // written directly by flash
__device__ __nv_bfloat16 g_WVl[MROWS*NSTATE];
__device__ __nv_bfloat16 g_Wth[4*NSTATE*NSTATE];  // transposed weights [n][k]; q,k,v,o contiguous
__device__ __nv_bfloat16 g_Wtl[4*NSTATE*NSTATE];

// ---------------- helpers ---------------------------------------------------
__device__ __forceinline__ void split_bf16(float v, __nv_bfloat16& h, __nv_bfloat16& l) {
    h = __float2bfloat16_rn(v);
    l = __float2bfloat16_rn(v - __bfloat162float(h));
}
__device__ __forceinline__ void packsplit2(float x, float y, uint32_t& hh, uint32_t& ll) {
    __nv_bfloat16 xh, xl, yh, yl;
    split_bf16(x, xh, xl); split_bf16(y, yh, yl);
    __nv_bfloat162 hv, lv;
    hv.x = xh; hv.y = yh; lv.x = xl; lv.y = yl;
    hh = *(uint32_t*)&hv; ll = *(uint32_t*)&lv;
}
__device__ __forceinline__ void mma16816(float* c, const uint32_t* a, const uint32_t* b) {
    asm volatile(
        "mma.sync.aligned.m16n8k16.row.col.f32.bf16.bf16.f32 "
        "{%0,%1,%2,%3}, {%4,%5,%6,%7}, {%8,%9}, {%0,%1,%2,%3};"
        : "+f"(c[0]), "+f"(c[1]), "+f"(c[2]), "+f"(c[3])
        : "r"(a[0]), "r"(a[1]), "r"(a[2]), "r"(a[3]), "r"(b[0]), "r"(b[1]));
}
__device__ __forceinline__ void mma2(float* c0, float* c1, const uint32_t* a, const uint32_t* r4) {
    mma16816(c0, a, r4);
    mma16816(c1, a, r4 + 2);
}
__device__ __forceinline__ void ldsm4(uint32_t* r, uint32_t saddr) {
    asm volatile("ldmatrix.sync.aligned.m8n8.x4.shared.b16 {%0,%1,%2,%3}, [%4];"
        : "=r"(r[0]), "=r"(r[1]), "=r"(r[2]), "=r"(r[3]) : "r"(saddr));
}
__device__ __forceinline__ void cp16(void* smem_dst, const void* gsrc) {
    uint32_t s = (uint32_t)__cvta_generic_to_shared(smem_dst);
    asm volatile("cp.async.ca.shared.global [%0], [%1], 16;" :: "r"(s), "l"(gsrc) : "memory");
}
#define CP_COMMIT() asm volatile("cp.async.commit_group;" ::: "memory")
#define CP_WAIT(n)  asm volatile("cp.async.wait_group %0;" :: "n"(n) : "memory")

// ---------------- conversion kernels ----------------------------------------
__global__ void convert_x_kernel(const float* __restrict__ x) {
    size_t i = (size_t)blockIdx.x * 256 + threadIdx.x;
    float4 v = ((const float4*)x)[i];
    __nv_bfloat16 h[4], l[4];
    split_bf16(v.x, h[0], l[0]); split_bf16(v.y, h[1], l[1]);
    split_bf16(v.z, h[2], l[2]); split_bf16(v.w, h[3], l[3]);
    ((uint2*)g_xh)[i] = *(uint2*)h;
    ((uint2*)g_xl)[i] = *(uint2*)l;
}

__global__ void transpose_convert(const float* __restrict__ W0, const float* __restrict__ W1,
                                  const float* __restrict__ W2, const float* __restrict__ W3) {
    __shared__ float T[32][33];
    int w = blockIdx.z;
    const float* W = (w == 0) ? W0 : (w == 1) ? W1 : (w == 2) ? W2 : W3;
    int n0 = blockIdx.x * 32, k0 = blockIdx.y * 32;
    int tx = threadIdx.x, ty = threadIdx.y;
#pragma unroll
    for (int r = 0; r < 4; r++) {
        int kl = ty + 8 * r;
        T[kl][tx] = W[(size_t)(k0 + kl) * NSTATE + n0 + tx];
    }
    __syncthreads();
    size_t base = (size_t)w * NSTATE * NSTATE;
#pragma unroll
    for (int r = 0; r < 4; r++) {
        int nl = ty + 8 * r;
        float v = T[tx][nl];
        __nv_bfloat16 h, l;
        split_bf16(v, h, l);
        size_t o = base + (size_t)(n0 + nl) * NSTATE + k0 + tx;
        g_Wth[o] = h;
        g_Wtl[o] = l;
    }
}

// V transpose: g_V[b,h,s,d] fp32 -> g_Vt{h,l}[b,h,d,s] bf16
__global__ void vtrans() {
    __shared__ float T[32][33];
    int bh = blockIdx.z;
    int s0 = blockIdx.x * 32, d0 = blockIdx.y * 32;
    int tx = threadIdx.x, ty = threadIdx.y;
    const float* src = g_V + (size_t)bh * SDIM * HDIM;
#pragma unroll
    for (int r = 0; r < 4; r++)
        T[ty + 8 * r][tx] = src[(size_t)(s0 + ty + 8 * r) * HDIM + d0 + tx];
    __syncthreads();
#pragma unroll
    for (int r = 0; r < 4; r++) {
        int d = d0 + ty + 8 * r;
        float v = T[tx][ty + 8 * r];
        __nv_bfloat16 h, lo;
        split_bf16(v, h, lo);
        size_t o = ((size_t)bh * HDIM + d) * SDIM + s0 + tx;
        g_Vth[o] = h;
        g_Vtl[o] = lo;
    }
}

// ---------------- warp-mma bf16 hi/lo GEMM (cp.async + ldmatrix) -------------
// fused=1: C(4096x3072) = x @ [Wq|Wk|Wv] (dest Q/K/V per 1024-col group)
// fused=0: C(4096x1024) = WV @ Wo -> Cext
#define LDW 40
#define GT_TILE (128*LDW)          // elements per 128x32 tile
#define GT_STAGE (4*GT_TILE)       // Ah, Al, Bh, Bl
#define GEMM_SMEM (2*GT_STAGE*2)   // bytes (2 stages, bf16) = 81920
#define NCHUNK 32                  // K=1024 / 32

__global__ void __launch_bounds__(256, 2)
gemm_mma(const float* __restrict__ bq, const float* __restrict__ bv,
         const float* __restrict__ bo, float* __restrict__ Cext, int fused)
{
    extern __shared__ __nv_bfloat16 dynsm[];

    int tid = threadIdx.x;
    int wid = tid >> 5, l = tid & 31;
    int wm = wid >> 2, wn = wid & 3;
    int mw0 = wm * 64, nw0 = wn * 32;
    int m0 = blockIdx.y * 128;
    int n0g = blockIdx.x * 128;                 // global col (fused: 0..3071)
    int j = fused ? (n0g >> 10) : 3;            // 0=Q 1=K 2=V 3=out
    int gr = l >> 2, kc = (l & 3) * 2;

    const __nv_bfloat16* A_h = fused ? g_xh : g_WVh;
    const __nv_bfloat16* A_l = fused ? g_xl : g_WVl;
    size_t brow = (size_t)(fused ? n0g : 3 * NSTATE + n0g) * NSTATE;
    const __nv_bfloat16* srcs[4] = { A_h, A_l, g_Wth + brow, g_Wtl + brow };
    int rb[4] = { m0, m0, 0, 0 };

    // per-lane ldmatrix address components
    int aRowIn = (l & 7) + ((l >> 3) & 1) * 8;
    int aColSel = (l >> 4) * 8;
    uint32_t aoff = (uint32_t)(((mw0 + aRowIn) * LDW + aColSel) * 2);
    int bRowIn = (l & 7) + (l >> 4) * 8;
    int bColSel = ((l >> 3) & 1) * 8;
    uint32_t boff = (uint32_t)(((nw0 + bRowIn) * LDW + bColSel) * 2);
    uint32_t smemBase = (uint32_t)__cvta_generic_to_shared(dynsm);

    float c[4][4][4];
#pragma unroll
    for (int mt = 0; mt < 4; mt++)
#pragma unroll
        for (int nt = 0; nt < 4; nt++)
#pragma unroll
            for (int e = 0; e < 4; e++) c[mt][nt][e] = 0.f;

    auto loadStage = [&](int chunk, int p) {
        int k0 = chunk * 32;
        __nv_bfloat16* st = dynsm + p * GT_STAGE;
#pragma unroll
        for (int i = 0; i < 8; i++) {
            int idx = tid + i * 256;
            int t = idx >> 9, e = idx & 511;
            int row = e >> 2, seg = e & 3;
            cp16(st + t * GT_TILE + row * LDW + seg * 8,
                 srcs[t] + (size_t)(rb[t] + row) * NSTATE + k0 + seg * 8);
        }
    };

    loadStage(0, 0);
    CP_COMMIT();

    for (int it = 0; it < NCHUNK; it++) {
        int p = it & 1;
        if (it + 1 < NCHUNK) {
            loadStage(it + 1, p ^ 1);
            CP_COMMIT();
            CP_WAIT(1);
        } else {
            CP_WAIT(0);
        }
        __syncthreads();

        uint32_t sb = smemBase + p * (GT_STAGE * 2);
#pragma unroll
        for (int kk = 0; kk < 32; kk += 16) {
            uint32_t bh[4][2], bl[4][2];
#pragma unroll
            for (int np = 0; np < 2; np++) {
                uint32_t stepB = (uint32_t)((np * 16 * LDW + kk) * 2);
                uint32_t r[4];
                ldsm4(r, sb + 2 * GT_TILE * 2 + boff + stepB);
                bh[np * 2][0] = r[0]; bh[np * 2][1] = r[1];
                bh[np * 2 + 1][0] = r[2]; bh[np * 2 + 1][1] = r[3];
                ldsm4(r, sb + 3 * GT_TILE * 2 + boff + stepB);
                bl[np * 2][0] = r[0]; bl[np * 2][1] = r[1];
                bl[np * 2 + 1][0] = r[2]; bl[np * 2 + 1][1] = r[3];
            }
#pragma unroll
            for (int mt = 0; mt < 4; mt++) {
                uint32_t stepA = (uint32_t)((mt * 16 * LDW + kk) * 2);
                uint32_t ah[4], al[4];
                ldsm4(ah, sb + aoff + stepA);
                ldsm4(al, sb + GT_TILE * 2 + aoff + stepA);
#pragma unroll
                for (int nt = 0; nt < 4; nt++) mma16816(c[mt][nt], ah, bh[nt]);
#pragma unroll
                for (int nt = 0; nt < 4; nt++) mma16816(c[mt][nt], ah, bl[nt]);
#pragma unroll
                for (int nt = 0; nt < 4; nt++) mma16816(c[mt][nt], al, bh[nt]);
            }
        }
        __syncthreads();
    }

    // epilogue
    float scl = (j < 2) ? SCALE_QK : 1.0f;
#pragma unroll
    for (int mt = 0; mt < 4; mt++) {
#pragma unroll
        for (int nt = 0; nt < 4; nt++) {
            int ncol = n0g + nw0 + nt * 8 + kc;
            int nn = ncol & (NSTATE - 1);
            float b0 = 0.f, b1 = 0.f;
            if (j == 0)      { b0 = bq[nn]; b1 = bq[nn + 1]; }
            else if (j == 2) { b0 = bv[nn]; b1 = bv[nn + 1]; }
            else if (j == 3) { b0 = bo[nn]; b1 = bo[nn + 1]; }
#pragma unroll
            for (int half = 0; half < 2; half++) {
                int m = m0 + mw0 + mt * 16 + gr + half * 8;
                float v0 = (c[mt][nt][half * 2 + 0] + b0) * scl;
                float v1 = (c[mt][nt][half * 2 + 1] + b1) * scl;
                if (j == 3) {
                    *(float2*)(Cext + (size_t)m * NSTATE + nn) = make_float2(v0, v1);
                } else {
                    int b = m >> 11, s = m & (SDIM - 1);
                    int h2 = nn >> 6, d = nn & (HDIM - 1);
                    size_t o = ((size_t)(b * NHEAD + h2) * SDIM + s) * HDIM + d;
                    if (j == 2) {
                        *(float2*)(g_V + o) = make_float2(v0, v1);
                    } else {
                        uint32_t uh, ul;
                        packsplit2(v0, v1, uh, ul);
                        __nv_bfloat16* dh = j ? g_Kh : g_Qh;
                        __nv_bfloat16* dl = j ? g_Kl : g_Ql;
                        *(uint32_t*)&dh[o] = uh;
                        *(uint32_t*)&dl[o] = ul;
                    }
                }
            }
        }
    }
}

// ---------------- tensor-core flash attention (cp.async + ldmatrix) ---------
// Also writes the fully-masked region of qk (-1e9) — fill_mask is absorbed.
// Writes WV directly as bf16 hi/lo (convert_wv is absorbed).
#define LDK 72
#define KV_TILE (64*LDK)                 // one 64-row tile
#define KV_STAGE (4*KV_TILE)             // Kh, Kl, Vh, Vl
#define FLASH_SMEM ((128*2*LDK + 2*KV_STAGE) * 2)   // 110592 bytes

__global__ __launch_bounds__(256)
void flash_mma(float* __restrict__ qk_out)
{
    extern __shared__ __nv_bfloat16 sm[];
    __nv_bfloat16* Qh = sm;
    __nv_bfloat16* Ql = Qh + 128 * LDK;
    __nv_bfloat16* KV = Ql + 128 * LDK;   // 2 stages x [Kh|Kl|Vh|Vl]

    int qb = gridDim.x - 1 - blockIdx.x;    // big tiles first
    int hh = blockIdx.y, b = blockIdx.z;
    int bh = b * NHEAD + hh;
    int q0 = qb * 128;
    int tid = threadIdx.x, w = tid >> 5, l = tid & 31;
    int gr = l >> 2, kc = (l & 3) * 2;
    int q0w = q0 + w * 16;

    const __nv_bfloat16* Qhg = g_Qh + (size_t)bh * SDIM * HDIM;
    const __nv_bfloat16* Qlg = g_Ql + (size_t)bh * SDIM * HDIM;
    const __nv_bfloat16* Khg = g_Kh + (size_t)bh * SDIM * HDIM;
    const __nv_bfloat16* Klg = g_Kl + (size_t)bh * SDIM * HDIM;
    const __nv_bfloat16* Vhg = g_Vth + (size_t)bh * HDIM * SDIM;
    const __nv_bfloat16* Vlg = g_Vtl + (size_t)bh * HDIM * SDIM;

    // Q block [128][64] hi/lo (plain loads; one-time)
#pragma unroll
    for (int i = 0; i < 4; i++) {
        int e = tid + i * 256;
        int row = e >> 3, col = (e & 7) * 8;
        *(uint4*)&Qh[row * LDK + col] = *(const uint4*)(Qhg + (size_t)(q0 + row) * HDIM + col);
        *(uint4*)&Ql[row * LDK + col] = *(const uint4*)(Qlg + (size_t)(q0 + row) * HDIM + col);
    }

    auto loadKV = [&](int t, int p) {
        int k0 = t * 64;
        __nv_bfloat16* st = KV + p * KV_STAGE;
#pragma unroll
        for (int i = 0; i < 8; i++) {
            int idx = tid + i * 256;               // 0..2047
            int arr = idx >> 9;                    // 0..3
            int e = idx & 511;
            int row = e >> 3, seg = e & 7;
            const __nv_bfloat16* src;
            if (arr == 0)      src = Khg + (size_t)(k0 + row) * HDIM + seg * 8;
            else if (arr == 1) src = Klg + (size_t)(k0 + row) * HDIM + seg * 8;
            else if (arr == 2) src = Vhg + (size_t)row * SDIM + k0 + seg * 8;
            else               src = Vlg + (size_t)row * SDIM + k0 + seg * 8;
            cp16(st + arr * KV_TILE + row * LDK + seg * 8, src);
        }
    };

    int nT = qb * 2 + 2;
    loadKV(0, 0);
    CP_COMMIT();

    // ---- absorbed causal fill: this warp's rows, cols [kfillw, SDIM) ----
    {
        int kfillw = ((q0w + 16 + 63) >> 6) << 6;
        float4 neg4 = make_float4(-1e9f, -1e9f, -1e9f, -1e9f);
#pragma unroll 1
        for (int r = 0; r < 16; r++) {
            float* base = qk_out + ((size_t)bh * SDIM + q0w + r) * SDIM;
            for (int c4 = (kfillw >> 2) + l; c4 < (SDIM >> 2); c4 += 32)
                *(float4*)(base + c4 * 4) = neg4;
        }
    }

    // ldmatrix lane address components
    uint32_t smemU = (uint32_t)__cvta_generic_to_shared(sm);
    int aRowIn = (l & 7) + ((l >> 3) & 1) * 8;
    int aColSel = (l >> 4) * 8;
    uint32_t aoff = (uint32_t)(((w * 16 + aRowIn) * LDK + aColSel) * 2);
    int bRowIn = (l & 7) + (l >> 4) * 8;
    int bColSel = ((l >> 3) & 1) * 8;
    uint32_t boff = (uint32_t)((bRowIn * LDK + bColSel) * 2);
    uint32_t qhB = smemU + aoff;
    uint32_t qlB = smemU + 128 * LDK * 2 + aoff;
    uint32_t kvB = smemU + 256 * LDK * 2;

    float oacc[8][4];
#pragma unroll
    for (int nd = 0; nd < 8; nd++)
#pragma unroll
        for (int e = 0; e < 4; e++) oacc[nd][e] = 0.f;
    float mrow[2] = {-INFINITY, -INFINITY};
    float lrow[2] = {0.f, 0.f};

    for (int t = 0; t < nT; t++) {
        int p = t & 1;
        int k0 = t * 64;
        if (t + 1 < nT) {
            loadKV(t + 1, p ^ 1);
            CP_COMMIT();
            CP_WAIT(1);
        } else {
            CP_WAIT(0);
        }
        __syncthreads();

        if (k0 <= q0w + 15) {
            uint32_t bKh = kvB + (p * KV_STAGE + 0 * KV_TILE) * 2 + boff;
            uint32_t bKl = kvB + (p * KV_STAGE + 1 * KV_TILE) * 2 + boff;
            uint32_t bVh = kvB + (p * KV_STAGE + 2 * KV_TILE) * 2 + boff;
            uint32_t bVl = kvB + (p * KV_STAGE + 3 * KV_TILE) * 2 + boff;

            float sacc[8][4];
#pragma unroll
            for (int nt = 0; nt < 8; nt++)
#pragma unroll
                for (int e = 0; e < 4; e++) sacc[nt][e] = 0.f;

            // ---- S = Q K^T (product-major over jj: acc reuse distance 8) ----
#pragma unroll
            for (int kk = 0; kk < 4; kk++) {
                uint32_t stepQ = (uint32_t)(kk * 16 * 2);
                uint32_t ah[4], al[4];
                ldsm4(ah, qhB + stepQ);
                ldsm4(al, qlB + stepQ);
                uint32_t rh[4][4], rl[4][4];
#pragma unroll
                for (int jj = 0; jj < 4; jj++) {
                    uint32_t stepB = (uint32_t)((jj * 16 * LDK + kk * 16) * 2);
                    ldsm4(rh[jj], bKh + stepB);
                    ldsm4(rl[jj], bKl + stepB);
                }
#pragma unroll
                for (int jj = 0; jj < 4; jj++)
                    mma2(sacc[2 * jj], sacc[2 * jj + 1], ah, rh[jj]);
#pragma unroll
                for (int jj = 0; jj < 4; jj++)
                    mma2(sacc[2 * jj], sacc[2 * jj + 1], ah, rl[jj]);
#pragma unroll
                for (int jj = 0; jj < 4; jj++)
                    mma2(sacc[2 * jj], sacc[2 * jj + 1], al, rh[jj]);
            }

            if (k0 + 63 > q0w) {
#pragma unroll
                for (int nt = 0; nt < 8; nt++)
#pragma unroll
                    for (int e = 0; e < 4; e++) {
                        int kg = k0 + nt * 8 + kc + (e & 1);
                        int qg = q0w + gr + ((e >> 1) ? 8 : 0);
                        if (kg > qg) sacc[nt][e] = -1e9f;
                    }
            }

            float* qp = qk_out + ((size_t)bh * SDIM + q0w + gr) * SDIM + k0;
#pragma unroll
            for (int nt = 0; nt < 8; nt++) {
                *(float2*)(qp + nt * 8 + kc) = make_float2(sacc[nt][0], sacc[nt][1]);
                *(float2*)(qp + 8 * SDIM + nt * 8 + kc) = make_float2(sacc[nt][2], sacc[nt][3]);
            }

            // ---- online softmax ----
#pragma unroll
            for (int half = 0; half < 2; half++) {
                int e0 = half * 2;
                float tmax = -INFINITY;
#pragma unroll
                for (int nt = 0; nt < 8; nt++)
                    tmax = fmaxf(tmax, fmaxf(sacc[nt][e0], sacc[nt][e0 + 1]));
                tmax = fmaxf(tmax, __shfl_xor_sync(0xffffffffu, tmax, 1));
                tmax = fmaxf(tmax, __shfl_xor_sync(0xffffffffu, tmax, 2));
                float mnew = fmaxf(mrow[half], tmax);
                float fac = __expf(mrow[half] - mnew);
                mrow[half] = mnew;
                float ps = 0.f;
#pragma unroll
                for (int nt = 0; nt < 8; nt++) {
                    float p0 = __expf(sacc[nt][e0] - mnew);
                    float p1 = __expf(sacc[nt][e0 + 1] - mnew);
                    sacc[nt][e0] = p0; sacc[nt][e0 + 1] = p1;
                    ps += p0 + p1;
                }
                lrow[half] = lrow[half] * fac + ps;
#pragma unroll
                for (int nd = 0; nd < 8; nd++) {
                    oacc[nd][e0] *= fac;
                    oacc[nd][e0 + 1] *= fac;
                }
            }

            // ---- O += P V (product-major over jj) ----
#pragma unroll
            for (int kk = 0; kk < 4; kk++) {
                uint32_t ph[4], pl[4];
                packsplit2(sacc[2 * kk][0],     sacc[2 * kk][1],     ph[0], pl[0]);
                packsplit2(sacc[2 * kk][2],     sacc[2 * kk][3],     ph[1], pl[1]);
                packsplit2(sacc[2 * kk + 1][0], sacc[2 * kk + 1][1], ph[2], pl[2]);
                packsplit2(sacc[2 * kk + 1][2], sacc[2 * kk + 1][3], ph[3], pl[3]);
                uint32_t vh[4][4], vl[4][4];
#pragma unroll
                for (int jj = 0; jj < 4; jj++) {
                    uint32_t stepB = (uint32_t)((jj * 16 * LDK + kk * 16) * 2);
                    ldsm4(vh[jj], bVh + stepB);
                    ldsm4(vl[jj], bVl + stepB);
                }
#pragma unroll
                for (int jj = 0; jj < 4; jj++)
                    mma2(oacc[2 * jj], oacc[2 * jj + 1], ph, vh[jj]);
#pragma unroll
                for (int jj = 0; jj < 4; jj++)
                    mma2(oacc[2 * jj], oacc[2 * jj + 1], ph, vl[jj]);
#pragma unroll
                for (int jj = 0; jj < 4; jj++)
                    mma2(oacc[2 * jj], oacc[2 * jj + 1], pl, vh[jj]);
            }
        }
        __syncthreads();
    }

#pragma unroll
    for (int half = 0; half < 2; half++) {
        lrow[half] += __shfl_xor_sync(0xffffffffu, lrow[half], 1);
        lrow[half] += __shfl_xor_sync(0xffffffffu, lrow[half], 2);
    }
    float inv0 = 1.f / lrow[0], inv1 = 1.f / lrow[1];
    // direct bf16 hi/lo WV output (bit-identical to post-hoc convert_wv split)
#pragma unroll
    for (int nd = 0; nd < 8; nd++) {
        int d = nd * 8 + kc;
        int q = q0w + gr;
        size_t o0 = ((size_t)(b * SDIM + q) * NHEAD + hh) * HDIM + d;
        size_t o1 = ((size_t)(b * SDIM + q + 8) * NHEAD + hh) * HDIM + d;
        uint32_t uh, ul;
        packsplit2(oacc[nd][0] * inv0, oacc[nd][1] * inv0, uh, ul);
        *(uint32_t*)&g_WVh[o0] = uh;
        *(uint32_t*)&g_WVl[o0] = ul;
        packsplit2(oacc[nd][2] * inv1, oacc[nd][3] * inv1, uh, ul);
        *(uint32_t*)&g_WVh[o1] = uh;
        *(uint32_t*)&g_WVl[o1] = ul;
    }
}

// ---------------------------------------------------------------------------
extern "C" void kernel_launch(void* const* d_in, const int* in_sizes, int n_in,
                              void* d_out, int out_size)
{
    const float* x  = (const float*)d_in[0];
    const float* Wq = (const float*)d_in[2];
    const float* bq = (const float*)d_in[3];
    const float* Wk = (const float*)d_in[4];
    const float* Wv = (const float*)d_in[5];
    const float* bv = (const float*)d_in[6];
    const float* Wo = (const float*)d_in[7];
    const float* bo = (const float*)d_in[8];

    float* out = (float*)d_out;                       // [b,s,1024]
    float* qk  = out + (size_t)BDIM * SDIM * NSTATE;  // [b,h,s,s]

    static bool attr_set = false;
    if (!attr_set) {
        cudaFuncSetAttribute(flash_mma, cudaFuncAttributeMaxDynamicSharedMemorySize, FLASH_SMEM);
        cudaFuncSetAttribute(gemm_mma, cudaFuncAttributeMaxDynamicSharedMemorySize, GEMM_SMEM);
        attr_set = true;
    }

    convert_x_kernel<<<MROWS * NSTATE / 4 / 256, 256>>>(x);
    transpose_convert<<<dim3(32, 32, 4), dim3(32, 8)>>>(Wq, Wk, Wv, Wo);

    // fused QKV projection: N = 3072
    gemm_mma<<<dim3(24, 32), 256, GEMM_SMEM>>>(bq, bv, nullptr, nullptr, 1);

    vtrans<<<dim3(SDIM / 32, HDIM / 32, BDIM * NHEAD), dim3(32, 8)>>>();

    flash_mma<<<dim3(SDIM / 128, NHEAD, BDIM), 256, FLASH_SMEM>>>(qk);

    gemm_mma<<<dim3(8, 32), 256, GEMM_SMEM>>>(nullptr, nullptr, bo, out, 0);
}